// round 17
// baseline (speedup 1.0000x reference)
#include <cuda_runtime.h>
#include <cuda_fp16.h>
#include <math.h>

#define Bb 32
#define EPSV 0.05f
#define INV_EPS 20.0f
#define SHIFT 10.0f
#define NITERS 50
#define NTHR 512            // 16 warps; warp owns 8 rows

// ---------------------------------------------------------------------------
__device__ __forceinline__ unsigned smem_u32(const void* p) {
    unsigned a;
    asm("{ .reg .u64 t; cvta.to.shared.u64 t, %1; cvt.u32.u64 %0, t; }"
        : "=r"(a) : "l"(p));
    return a;
}
__device__ __forceinline__ unsigned mapa_rank(unsigned addr, int rank) {
    unsigned r;
    asm("mapa.shared::cluster.u32 %0, %1, %2;" : "=r"(r) : "r"(addr), "r"(rank));
    return r;
}
__device__ __forceinline__ void st_cluster_f32(unsigned addr, float v) {
    asm volatile("st.shared::cluster.f32 [%0], %1;" :: "r"(addr), "f"(v));
}
#define CLUSTER_SYNC() do { \
    asm volatile("barrier.cluster.arrive.aligned;" ::: "memory"); \
    asm volatile("barrier.cluster.wait.aligned;"   ::: "memory"); \
} while (0)

// ---------------------------------------------------------------------------
// ONE kernel. grid = 128, block = 512, cluster(4) = 1 batch.
// smem: ev[512] | cpart[16*512] | inbox[2][4][512] | row_mn[128] | sc_s[128]
//       | u_s[128] | ot_in[4] | pad[4] | tile half[128*512]   (tile 16B-aligned)
__global__ void __launch_bounds__(NTHR, 1) __cluster_dims__(4, 1, 1)
emd_fused_kernel(const float* __restrict__ a_mask, const float* __restrict__ pc_a,
                 const float* __restrict__ b_mask, const float* __restrict__ pc_b,
                 float* __restrict__ out)
{
    extern __shared__ float smem[];
    float*  ev     = smem;                        // 512
    float*  cpart  = smem + 512;                  // 8192
    float*  inbox  = smem + 512 + 8192;           // 4096 (2 buf x 4 slot x 512)
    float*  row_mn = smem + 512 + 8192 + 4096;    // 128
    float*  sc_s   = row_mn + 128;                // 128 (it0 row scales)
    float*  u_s    = sc_s + 128;                  // 128 (final u-scalings)
    float*  ot_in  = u_s + 128;                   // 4 (+4 pad)
    __half* tile   = (__half*)(ot_in + 8);        // 16B-aligned (ofs 13192 f)

    const int batch = blockIdx.x >> 2, slot = blockIdx.x & 3;
    const int row_base = slot * 128;
    const int t = threadIdx.x, w = t >> 5, lane = t & 31;

    // ---------------- prep (each CTA computes full-batch stats) -------------
    int gb = batch * 512 + t;
    float apt = a_mask[gb] * pc_a[gb * 3 + 2];
    float bpt = b_mask[gb] * pc_b[gb * 3 + 2];
    inbox[t] = apt;                               // stash (buffer0, dead by it1)
    cpart[t] = apt; cpart[512 + t] = bpt; cpart[1024 + t] = (bpt > 0.f) ? 0.f : 1.f;
    __syncthreads();
    for (int o = 256; o; o >>= 1) {
        if (t < o) {
            cpart[t]        += cpart[t + o];
            cpart[512 + t]  += cpart[512 + t + o];
            cpart[1024 + t] += cpart[1024 + t + o];
        }
        __syncthreads();
    }
    const float sa = cpart[0], sb = cpart[512], mmask = cpart[1024];
    const float bh = bpt / sb;                    // masked -> 0
    __syncthreads();

    // overlay b columns into cpart
    cpart[t]        = pc_b[gb * 3 + 0];
    cpart[512 + t]  = pc_b[gb * 3 + 1];
    cpart[1024 + t] = bpt;
    __syncthreads();
    const float* bxs = cpart;
    const float* bys = cpart + 512;
    const float* bvs = cpart + 1024;

    // ---------------- build SMEM tile ----------------
    // t_ij = exp((dmin_i - d_ij)*INV_EPS + SHIFT), 0 for masked pairs.
    float ahr[8];
#pragma unroll
    for (int r = 0; r < 8; r++) {
        int row  = w * 8 + r;
        int grow = batch * 512 + row_base + row;
        float ax = pc_a[grow * 3 + 0], ay = pc_a[grow * 3 + 1];
        float ah = inbox[row_base + row] / sa;
        ahr[r] = ah;

        float dv[16], mn = 1e30f;
#pragma unroll
        for (int k = 0; k < 16; k++) {
            int j = k * 32 + lane;
            float dx = ax - bxs[j], dy = ay - bys[j];
            float d = sqrtf(__fmaf_rn(dx, dx, __fmaf_rn(dy, dy, 1e-12f)));
            dv[k] = d;
            if (bvs[j] > 0.f) mn = fminf(mn, d);
        }
#pragma unroll
        for (int o = 16; o; o >>= 1) mn = fminf(mn, __shfl_xor_sync(0xFFFFFFFFu, mn, o));
        if (lane == 0) {
            row_mn[row] = mn;
            sc_s[row]   = __expf(-__fmaf_rn(INV_EPS, mn, SHIFT)); // e^{-20mn-SHIFT}
        }

#pragma unroll
        for (int k = 0; k < 16; k++) {
            int j = k * 32 + lane;
            float arg = fminf((mn - dv[k]) * INV_EPS, 0.f) + SHIFT;
            float tv  = (bvs[j] > 0.f && ah > 0.f) ? __expf(arg) : 0.f;
            tile[row * 512 + j] = __float2half(tv);
        }
    }
    __syncthreads();                 // overlay dead; tile+sc_s complete

    const unsigned my0 = smem_u32(&inbox[slot * 512 + t]);  // buffer0 slot word
    const unsigned my1 = my0 + 2048u * 4u;                  // buffer1
    unsigned pa0[4], pa1[4];
#pragma unroll
    for (int rk = 0; rk < 4; rk++) {
        pa0[rk] = mapa_rank(my0, rk);
        pa1[rk] = mapa_rank(my1, rk);
    }

    CLUSTER_SYNC();

    float c[16], sv[16], x[16];

#define LOAD_SV() do {                                                       \
        const float4* ev4_ = (const float4*)ev;                              \
        float4 e0 = ev4_[lane * 2],      e1 = ev4_[lane * 2 + 1];            \
        float4 e2 = ev4_[64 + lane * 2], e3 = ev4_[64 + lane * 2 + 1];       \
        sv[0]=e0.x; sv[1]=e0.y; sv[2]=e0.z; sv[3]=e0.w;                      \
        sv[4]=e1.x; sv[5]=e1.y; sv[6]=e1.z; sv[7]=e1.w;                      \
        sv[8]=e2.x; sv[9]=e2.y; sv[10]=e2.z; sv[11]=e2.w;                    \
        sv[12]=e3.x; sv[13]=e3.y; sv[14]=e3.z; sv[15]=e3.w;                  \
    } while (0)

#define LOAD_X(ROW) do {                                                     \
        const uint4* rp_ = (const uint4*)(tile + (ROW) * 512);               \
        uint4 q0 = rp_[lane], q1 = rp_[32 + lane];                           \
        float2 p_;                                                           \
        p_ = __half22float2(*(const __half2*)&q0.x); x[0]=p_.x;  x[1]=p_.y;  \
        p_ = __half22float2(*(const __half2*)&q0.y); x[2]=p_.x;  x[3]=p_.y;  \
        p_ = __half22float2(*(const __half2*)&q0.z); x[4]=p_.x;  x[5]=p_.y;  \
        p_ = __half22float2(*(const __half2*)&q0.w); x[6]=p_.x;  x[7]=p_.y;  \
        p_ = __half22float2(*(const __half2*)&q1.x); x[8]=p_.x;  x[9]=p_.y;  \
        p_ = __half22float2(*(const __half2*)&q1.y); x[10]=p_.x; x[11]=p_.y; \
        p_ = __half22float2(*(const __half2*)&q1.z); x[12]=p_.x; x[13]=p_.y; \
        p_ = __half22float2(*(const __half2*)&q1.w); x[14]=p_.x; x[15]=p_.y; \
    } while (0)

// Phase-split row pass:
//  1) 8 row-dots (x discarded each time)
//  2) ONE batched reduction phase: 5 shfl steps x 8 parallel chains
//  3) 8 independent divisions
//  4) reload x per row, accumulate columns
#define ROW_PASS(IS_FIRST, IS_LAST) do {                                     \
        float dot[8], uh[8];                                                 \
        _Pragma("unroll")                                                    \
        for (int r = 0; r < 8; r++) {                                        \
            LOAD_X(w * 8 + r);                                               \
            float d0, d1, d2, d3;                                            \
            if (IS_FIRST) {                                                  \
                d0 = (x[0]+x[1])+(x[2]+x[3]);   d1 = (x[4]+x[5])+(x[6]+x[7]);\
                d2 = (x[8]+x[9])+(x[10]+x[11]); d3 = (x[12]+x[13])+(x[14]+x[15]);\
            } else {                                                         \
                d0 = d1 = d2 = d3 = 0.f;                                     \
                _Pragma("unroll")                                            \
                for (int q = 0; q < 4; q++) {                                \
                    d0 = __fmaf_rn(x[q],      sv[q],      d0);               \
                    d1 = __fmaf_rn(x[4 + q],  sv[4 + q],  d1);               \
                    d2 = __fmaf_rn(x[8 + q],  sv[8 + q],  d2);               \
                    d3 = __fmaf_rn(x[12 + q], sv[12 + q], d3);               \
                }                                                            \
            }                                                                \
            dot[r] = (d0 + d1) + (d2 + d3);                                  \
        }                                                                    \
        _Pragma("unroll")                                                    \
        for (int o = 16; o; o >>= 1) {                                       \
            _Pragma("unroll")                                                \
            for (int r = 0; r < 8; r++)                                      \
                dot[r] += __shfl_xor_sync(0xFFFFFFFFu, dot[r], o);           \
        }                                                                    \
        _Pragma("unroll")                                                    \
        for (int r = 0; r < 8; r++) {                                        \
            if (IS_FIRST) {                                                  \
                float sc_ = sc_s[w * 8 + r];                                 \
                float den = __fmaf_rn(dot[r], sc_, mmask);                   \
                uh[r] = __fdividef(ahr[r] * sc_, fmaxf(den, 1e-35f));        \
            } else {                                                         \
                uh[r] = __fdividef(ahr[r], fmaxf(dot[r], 1e-35f));           \
            }                                                                \
            if (IS_LAST && lane == 0) u_s[w * 8 + r] = uh[r];                \
        }                                                                    \
        _Pragma("unroll")                                                    \
        for (int k = 0; k < 16; k++) c[k] = 0.f;                             \
        _Pragma("unroll")                                                    \
        for (int r = 0; r < 8; r++) {                                        \
            LOAD_X(w * 8 + r);                                               \
            _Pragma("unroll")                                                \
            for (int k = 0; k < 16; k++)                                     \
                c[k] = __fmaf_rn(x[k], uh[r], c[k]);                         \
        }                                                                    \
    } while (0)

// column-partial exchange into buffer BUFBIT of all 4 cluster CTAs.
#define EXCHANGE(BUFBIT) do {                                                \
        float4* cp = (float4*)(cpart + w * 512);                             \
        cp[lane * 2]      = make_float4(c[0],  c[1],  c[2],  c[3]);          \
        cp[lane * 2 + 1]  = make_float4(c[4],  c[5],  c[6],  c[7]);          \
        cp[64 + lane * 2] = make_float4(c[8],  c[9],  c[10], c[11]);         \
        cp[65 + lane * 2] = make_float4(c[12], c[13], c[14], c[15]);         \
        __syncthreads();                                                     \
        float s_ = 0.f;                                                      \
        _Pragma("unroll")                                                    \
        for (int w2 = 0; w2 < 16; w2++) s_ += cpart[w2 * 512 + t];           \
        const unsigned* pa_ = (BUFBIT) ? pa1 : pa0;                          \
        _Pragma("unroll")                                                    \
        for (int rk = 0; rk < 4; rk++) st_cluster_f32(pa_[rk], s_);          \
        CLUSTER_SYNC();                                                      \
    } while (0)

#define COMPUTE_EV(RBUF) do {                                                \
        const float* ib_ = inbox + (RBUF) * 2048;                            \
        float S_ = ib_[t] + ib_[512 + t] + ib_[1024 + t] + ib_[1536 + t];    \
        ev[t] = bh / fmaxf(S_, 1e-35f);                                      \
        __syncthreads();                                                     \
    } while (0)

    // ---- iteration 0 (ev = 1 everywhere; masked cols add Mmask*e^0) ----
    ROW_PASS(1, 0);
    EXCHANGE(1);                       // it0 writes buffer1

    // ---- iterations 1..48 ----
    for (int it = 1; it < NITERS - 1; ++it) {
        COMPUTE_EV(it & 1);            // read buffer it&1
        LOAD_SV();
        ROW_PASS(0, 0);
        EXCHANGE((it + 1) & 1);        // write buffer (it+1)&1
    }

    // ---- iteration 49 (record final u-scalings into u_s) ----
    COMPUTE_EV(1);
    LOAD_SV();
    ROW_PASS(0, 1);
    EXCHANGE(0);

    // ---------------- fused epilogue: OT term + huber ----------------
    COMPUTE_EV(0);                     // final ev
    LOAD_SV();

    float acc = 0.f;
#pragma unroll
    for (int r = 0; r < 8; r++) {
        float u = u_s[w * 8 + r];
        if (u > 0.f) {
            LOAD_X(w * 8 + r);
            float mnr = row_mn[w * 8 + r];
#pragma unroll
            for (int k = 0; k < 16; k++) {
                if (x[k] > 0.f) {
                    float d = __fmaf_rn(SHIFT - __logf(x[k]), EPSV, mnr);
                    acc = __fmaf_rn(d * d, u * x[k] * sv[k], acc);
                }
            }
        }
    }
#pragma unroll
    for (int o = 16; o; o >>= 1) acc += __shfl_xor_sync(0xFFFFFFFFu, acc, o);
    if (lane == 0) cpart[w] = acc;     // cpart free after last EXCHANGE
    __syncthreads();
    if (t == 0) {
        float s = 0.f;
#pragma unroll
        for (int k = 0; k < 16; k++) s += cpart[k];
        st_cluster_f32(mapa_rank(smem_u32(&ot_in[slot]), 0), s);
    }
    CLUSTER_SYNC();
    if (slot == 0 && t == 0) {
        float e = sa - sb, ae = fabsf(e);
        float hub = (ae <= 1.f) ? 0.5f * e * e : (ae - 0.5f);
        out[batch] = hub + ot_in[0] + ot_in[1] + ot_in[2] + ot_in[3];
    }

#undef LOAD_SV
#undef LOAD_X
#undef ROW_PASS
#undef EXCHANGE
#undef COMPUTE_EV
}

// ---------------------------------------------------------------------------
extern "C" void kernel_launch(void* const* d_in, const int* in_sizes, int n_in,
                              void* d_out, int out_size)
{
    const float* a_mask = (const float*)d_in[0];
    const float* pc_a   = (const float*)d_in[1];
    const float* b_mask = (const float*)d_in[2];
    const float* pc_b   = (const float*)d_in[3];
    float* out = (float*)d_out;

    // header (13192 floats, 16B-aligned end) + tile(fp16)
    static const int SMEM_BYTES =
        (512 + 16 * 512 + 8 * 512 + 128 + 128 + 128 + 8) * 4 + 128 * 512 * 2;
    cudaFuncSetAttribute(emd_fused_kernel,
                         cudaFuncAttributeMaxDynamicSharedMemorySize, SMEM_BYTES);

    emd_fused_kernel<<<4 * Bb, NTHR, SMEM_BYTES>>>(a_mask, pc_a, b_mask, pc_b, out);
}